// round 13
// baseline (speedup 1.0000x reference)
#include <cuda_runtime.h>
#include <cuda_bf16.h>
#include <cstdint>
#include <math.h>

#define NB    16
#define NPTS  1620
#define KNN_K 32
#define DD    64
#define CC    128
#define NSAMP (NB*NPTS*KNN_K)       // 829440 = 6480 tiles of 128
#define NTILE (NSAMP/128)           // 6480
#define TPB   405                   // tiles per batch
#define EPSV  1e-5f
#define GRIDP 148                   // persistent CTAs, 1 per SM

#define RSB    272                  // bf16 tile row stride bytes (136 elems: 128 + 8 pad)
#define TILE_B (128*RSB)            // 34816 B per 128x128 bf16 tile
#define STG_W  132                  // fp32 staging row stride (words)
// smem: [Bhi][Blo][Ahi][Alo][stage fp32 128x132][bn 1KB]
#define OFF_STAGE (4*TILE_B)                  // 139264
#define OFF_BN    (OFF_STAGE + 128*STG_W*4)   // 139264 + 67584 = 206848
#define SMEM_P    (OFF_BN + 1024)             // 207872 B

// ------------------------- scratch (static device globals) -------------------------
__device__ __align__(16) float g_featsT[NB*NPTS*DD];       // (b,n,d)
__device__ int   g_idx[NB*NPTS*KNN_K];
__device__ __align__(16) float g_y1[(size_t)NSAMP*CC];     // channel-major y1[c*NSAMP + s]
__device__ __align__(16) float g_pool[(size_t)NB*NPTS*CC]; // raw max over k, (b,n,c)
__device__ float g_stat[512];                              // [sum1|sq1|sum2|sq2] x 128
__device__ float g_scale[256];
__device__ float g_shift[256];

// ------------------------- helpers -------------------------
__device__ __forceinline__ uint32_t smem_u32(const void* p) {
    uint32_t a; asm("{ .reg .u64 t; cvta.to.shared.u64 t, %1; cvt.u32.u64 %0, t; }" : "=r"(a) : "l"(p));
    return a;
}
__device__ __forceinline__ void cpa16(uint32_t dst, const void* src) {
    asm volatile("cp.async.cg.shared.global [%0], [%1], 16;" :: "r"(dst), "l"(src) : "memory");
}
#define CP_COMMIT() asm volatile("cp.async.commit_group;" ::: "memory")
#define CP_WAIT0()  asm volatile("cp.async.wait_group 0;" ::: "memory")
__device__ __forceinline__ void ldsm_x4(uint32_t* r, uint32_t addr) {
    asm volatile("ldmatrix.sync.aligned.m8n8.x4.shared.b16 {%0,%1,%2,%3}, [%4];"
        : "=r"(r[0]), "=r"(r[1]), "=r"(r[2]), "=r"(r[3]) : "r"(addr));
}
__device__ __forceinline__ void mma_bf16(float* c, const uint32_t* a, const uint32_t* b) {
    asm volatile("mma.sync.aligned.m16n8k16.row.col.f32.bf16.bf16.f32 "
        "{%0,%1,%2,%3}, {%4,%5,%6,%7}, {%8,%9}, {%0,%1,%2,%3};"
        : "+f"(c[0]), "+f"(c[1]), "+f"(c[2]), "+f"(c[3])
        : "r"(a[0]), "r"(a[1]), "r"(a[2]), "r"(a[3]), "r"(b[0]), "r"(b[1]));
}
__device__ __forceinline__ uint32_t pack2(__nv_bfloat16 a, __nv_bfloat16 b) {
    return ((uint32_t)__bfloat16_as_ushort(b) << 16) | (uint32_t)__bfloat16_as_ushort(a);
}
// split 4 fp32 into bf16 hi + bf16 residual-lo; store 8B each (col local 0..127)
__device__ __forceinline__ void store_hl4(char* hiP, char* loP, int row, int col, float4 v) {
    const int off = row*RSB + col*2;
    const __nv_bfloat16 bx = __float2bfloat16(v.x), by = __float2bfloat16(v.y);
    const __nv_bfloat16 bz = __float2bfloat16(v.z), bw = __float2bfloat16(v.w);
    uint2 hh; hh.x = pack2(bx, by); hh.y = pack2(bz, bw);
    *(uint2*)(hiP + off) = hh;
    const __nv_bfloat16 lx = __float2bfloat16(v.x - __bfloat162float(bx));
    const __nv_bfloat16 ly = __float2bfloat16(v.y - __bfloat162float(by));
    const __nv_bfloat16 lz = __float2bfloat16(v.z - __bfloat162float(bz));
    const __nv_bfloat16 lw = __float2bfloat16(v.w - __bfloat162float(bw));
    uint2 ll; ll.x = pack2(lx, ly); ll.y = pack2(lz, lw);
    *(uint2*)(loP + off) = ll;
}

// ------------------------- 0: zero stats -------------------------
__global__ void zero_stats_kernel() {
    const int t = threadIdx.x;
#pragma unroll
    for (int i = 0; i < 4; ++i) g_stat[t + 128*i] = 0.f;
}

// ------------------------- 1: transpose x (B,D,N) -> featsT (B,N,D) -------------------------
__global__ __launch_bounds__(256) void transpose_kernel(const float* __restrict__ x)
{
    __shared__ float tile[16][DD + 1];
    const int b = blockIdx.x, n0 = blockIdx.y * 16;
    const int t = threadIdx.x;
    const int nn = t & 15, dbq = t >> 4;
#pragma unroll
    for (int i = 0; i < 4; ++i) {
        const int d = i*16 + dbq;
        const int n = n0 + nn;
        tile[nn][d] = (n < NPTS) ? x[((size_t)b*DD + d)*NPTS + n] : 0.f;
    }
    __syncthreads();
    const int d2 = t & 63, nb2 = t >> 6;
#pragma unroll
    for (int i = 0; i < 4; ++i) {
        const int nn2 = nb2 + i*4;
        const int n = n0 + nn2;
        if (n < NPTS) g_featsT[((size_t)b*NPTS + n)*DD + d2] = tile[nn2][d2];
    }
}

// ------------------------- 2: KNN warp-bitonic top-32 -------------------------
__device__ __forceinline__ void cmpswap_lex(float& d, int& i, int j, bool up) {
    const unsigned FULL = 0xffffffffu;
    const float od = __shfl_xor_sync(FULL, d, j);
    const int   oi = __shfl_xor_sync(FULL, i, j);
    const bool lower = ((threadIdx.x & j) == 0);
    const bool selfS = (d < od) || (d == od && i < oi);
    if (selfS != (lower == up)) { d = od; i = oi; }
}
__global__ __launch_bounds__(256) void knn_kernel(const float* __restrict__ coords)
{
    __shared__ float4 spts[NPTS];
    const unsigned FULL = 0xffffffffu;
    const int b = blockIdx.x, t = threadIdx.x;
    for (int i = t; i < NPTS; i += 256) {
        const float* cp = coords + (size_t)(b*NPTS + i)*3;
        const float px = cp[0], py = cp[1], pz = cp[2];
        spts[i] = make_float4(px, py, pz, px*px + py*py + pz*pz);
    }
    __syncthreads();
    const int warp = t >> 5, lane = t & 31;
    const int q = blockIdx.y * 8 + warp;
    if (q >= NPTS) return;
    const float4 me = spts[q];
    float kd = 3.4e38f;
    int   ki = (1 << 30) + lane;
    for (int m0 = 0; m0 < NPTS; m0 += 32) {
        const int m = m0 + lane;
        float d; int mi;
        if (m < NPTS) {
            const float4 o = spts[m];
            d = me.w + o.w - 2.f*(me.x*o.x + me.y*o.y + me.z*o.z);
            mi = m;
        } else { d = 3.4e38f; mi = (1 << 30) + lane; }
        const float thr  = __shfl_sync(FULL, kd, 31);
        const int   thrI = __shfl_sync(FULL, ki, 31);
        const bool better = (d < thr) || (d == thr && mi < thrI);
        if (__any_sync(FULL, better)) {
#pragma unroll
            for (int k = 2; k <= 32; k <<= 1) {
                const bool up = ((lane & k) == 0);
#pragma unroll
                for (int j = k >> 1; j >= 1; j >>= 1) cmpswap_lex(d, mi, j, up);
            }
            d  = __shfl_xor_sync(FULL, d, 31);
            mi = __shfl_xor_sync(FULL, mi, 31);
            const bool keepS = (kd < d) || (kd == d && ki < mi);
            float nd = keepS ? kd : d;
            int   ni = keepS ? ki : mi;
#pragma unroll
            for (int j = 16; j >= 1; j >>= 1) cmpswap_lex(nd, ni, j, true);
            kd = nd; ki = ni;
        }
    }
    g_idx[((size_t)b*NPTS + q)*KNN_K + lane] = ki;
}

// ------------------------- 3/5: persistent bf16x3 mma.sync GEMM + cp.async staging -------------------------
// 148 CTAs, each ~44 tiles. B resident. Next tile's fp32 inputs stream into smem staging
// via cp.async under the current tile's mma. Stats accumulate in regs, reduced at CTA end.
template<int LAYER>
__global__ __launch_bounds__(256, 1) void gemm_mma(const float* __restrict__ W)
{
    extern __shared__ char sb[];
    char* sBhi = sb;
    char* sBlo = sb + TILE_B;
    char* sAhi = sb + 2*TILE_B;
    char* sAlo = sb + 3*TILE_B;
    float* stageF = (float*)(sb + OFF_STAGE);
    float* sBN = (float*)(sb + OFF_BN);
    const int t = threadIdx.x, wid = t >> 5, lane = t & 31;
    const unsigned FULL = 0xffffffffu;
    const uint32_t base = smem_u32(sb);
    const uint32_t stageB = base + (uint32_t)OFF_STAGE;
    const int wr = wid & 3, wc = wid >> 2;
    const uint32_t arow = (uint32_t)((wr*32 + (lane & 15))*RSB + ((lane >> 4) * 8) * 2);
    const uint32_t brow = (uint32_t)((wc*64 + (lane & 7) + ((lane >> 4) << 3))*RSB + (((lane >> 3) & 1) * 8) * 2);
    const int sA = t >> 1, half = t & 1;

    // ---- one-time: B tile (W hi/lo, full K=128) + bn params
    {
        const int o = t >> 1;
        const float4* wrow = (const float4*)(W + (size_t)o*CC + half*64);
#pragma unroll
        for (int j = 0; j < 16; ++j)
            store_hl4(sBhi, sBlo, o, half*64 + j*4, wrow[j]);
    }
    if (LAYER == 1 && t < 128) { sBN[t] = g_scale[t]; sBN[128 + t] = g_shift[t]; }

    float fsum[16], fsq[16];
#pragma unroll
    for (int j = 0; j < 16; ++j) { fsum[j] = 0.f; fsq[j] = 0.f; }

    int tIdx = blockIdx.x;

    // ---- issue cp.async for first tile
    if (tIdx < NTILE) {
        if (LAYER == 0) {
            const int b = tIdx / TPB, r0 = (tIdx % TPB) * 128;
            const int n  = r0 / KNN_K + (sA >> 5);
            const int kk = sA & 31;
            const int nbr = g_idx[((size_t)b*NPTS + n)*KNN_K + kk];
            const float* nrow = g_featsT + (size_t)(b*NPTS + nbr)*DD + half*32;
            const float* crow = g_featsT + (size_t)(b*NPTS + n)*DD + half*32;
            const uint32_t d0 = stageB + (uint32_t)((sA*STG_W + half*32)*4);
            const uint32_t d1 = stageB + (uint32_t)((sA*STG_W + 64 + half*32)*4);
#pragma unroll
            for (int j = 0; j < 8; ++j) { cpa16(d0 + j*16, nrow + j*4); cpa16(d1 + j*16, crow + j*4); }
        } else {
            const int s0 = tIdx * 128;
#pragma unroll
            for (int i = 0; i < 4; ++i) {
                const int cb = (wid + i*8) * 4;
#pragma unroll
                for (int cc2 = 0; cc2 < 4; ++cc2) {
                    const int c = cb + cc2;
                    cpa16(stageB + (uint32_t)((c*STG_W + lane*4)*4),
                          g_y1 + (size_t)c*NSAMP + s0 + lane*4);
                }
            }
        }
        CP_COMMIT();
    }

    while (tIdx < NTILE) {
        CP_WAIT0();
        __syncthreads();   // staging visible to all; A-tile free (mma of prev tile done)

        // ---- convert staging -> A hi/lo
        if (LAYER == 0) {
#pragma unroll
            for (int j = 0; j < 8; ++j) {
                const float4 nv = *(const float4*)(stageF + sA*STG_W + half*32 + j*4);
                const float4 cv = *(const float4*)(stageF + sA*STG_W + 64 + half*32 + j*4);
                float4 d; d.x = nv.x-cv.x; d.y = nv.y-cv.y; d.z = nv.z-cv.z; d.w = nv.w-cv.w;
                const int dcol = half*32 + j*4;
                store_hl4(sAhi, sAlo, sA, dcol, d);         // diff features cols 0..63
                store_hl4(sAhi, sAlo, sA, 64 + dcol, cv);   // center features cols 64..127
            }
        } else {
#pragma unroll
            for (int i = 0; i < 4; ++i) {
                const int cb = (wid + i*8) * 4;
                const float s0c = sBN[cb+0], h0 = sBN[128+cb+0];
                const float s1c = sBN[cb+1], h1 = sBN[128+cb+1];
                const float s2c = sBN[cb+2], h2 = sBN[128+cb+2];
                const float s3c = sBN[cb+3], h3 = sBN[128+cb+3];
#pragma unroll
                for (int p = 0; p < 4; ++p) {
                    const int row = p*32 + lane;
                    float4 v;
                    v.x = fmaxf(fmaf(stageF[(cb+0)*STG_W + row], s0c, h0), 0.f);
                    v.y = fmaxf(fmaf(stageF[(cb+1)*STG_W + row], s1c, h1), 0.f);
                    v.z = fmaxf(fmaf(stageF[(cb+2)*STG_W + row], s2c, h2), 0.f);
                    v.w = fmaxf(fmaf(stageF[(cb+3)*STG_W + row], s3c, h3), 0.f);
                    store_hl4(sAhi, sAlo, row, cb, v);
                }
            }
        }
        __syncthreads();   // A ready; staging consumed -> free for next tile

        // ---- issue cp.async for next tile (flies under mma + epilogue)
        const int tNext = tIdx + GRIDP;
        if (tNext < NTILE) {
            if (LAYER == 0) {
                const int b = tNext / TPB, r0 = (tNext % TPB) * 128;
                const int n  = r0 / KNN_K + (sA >> 5);
                const int kk = sA & 31;
                const int nbr = g_idx[((size_t)b*NPTS + n)*KNN_K + kk];
                const float* nrow = g_featsT + (size_t)(b*NPTS + nbr)*DD + half*32;
                const float* crow = g_featsT + (size_t)(b*NPTS + n)*DD + half*32;
                const uint32_t d0 = stageB + (uint32_t)((sA*STG_W + half*32)*4);
                const uint32_t d1 = stageB + (uint32_t)((sA*STG_W + 64 + half*32)*4);
#pragma unroll
                for (int j = 0; j < 8; ++j) { cpa16(d0 + j*16, nrow + j*4); cpa16(d1 + j*16, crow + j*4); }
            } else {
                const int s0 = tNext * 128;
#pragma unroll
                for (int i = 0; i < 4; ++i) {
                    const int cb = (wid + i*8) * 4;
#pragma unroll
                    for (int cc2 = 0; cc2 < 4; ++cc2) {
                        const int c = cb + cc2;
                        cpa16(stageB + (uint32_t)((c*STG_W + lane*4)*4),
                              g_y1 + (size_t)c*NSAMP + s0 + lane*4);
                    }
                }
            }
            CP_COMMIT();
        }

        // ---- mma mainloop: fused 3 products, 8 k-steps
        float acc[2][8][4];
#pragma unroll
        for (int mi = 0; mi < 2; ++mi)
#pragma unroll
            for (int nf = 0; nf < 8; ++nf)
#pragma unroll
                for (int e = 0; e < 4; ++e) acc[mi][nf][e] = 0.f;

        const uint32_t aHp = base + 2u*(uint32_t)TILE_B + arow;
        const uint32_t aLp = aHp + (uint32_t)TILE_B;
        const uint32_t bHp = base + brow;
        const uint32_t bLp = bHp + (uint32_t)TILE_B;
#pragma unroll
        for (int ks = 0; ks < 8; ++ks) {
            const uint32_t ko = (uint32_t)(ks * 32);
            uint32_t ah0[4], ah1[4], al0[4], al1[4];
            ldsm_x4(ah0, aHp + ko);
            ldsm_x4(ah1, aHp + 16*RSB + ko);
            ldsm_x4(al0, aLp + ko);
            ldsm_x4(al1, aLp + 16*RSB + ko);
#pragma unroll
            for (int hb = 0; hb < 2; ++hb) {
                uint32_t bh[4][2], bl[4][2];
                {
                    uint32_t r[4], s[4];
                    ldsm_x4(r, bHp + (uint32_t)((hb*32)*RSB) + ko);
                    ldsm_x4(s, bHp + (uint32_t)((hb*32+16)*RSB) + ko);
                    bh[0][0]=r[0]; bh[0][1]=r[1]; bh[1][0]=r[2]; bh[1][1]=r[3];
                    bh[2][0]=s[0]; bh[2][1]=s[1]; bh[3][0]=s[2]; bh[3][1]=s[3];
                    ldsm_x4(r, bLp + (uint32_t)((hb*32)*RSB) + ko);
                    ldsm_x4(s, bLp + (uint32_t)((hb*32+16)*RSB) + ko);
                    bl[0][0]=r[0]; bl[0][1]=r[1]; bl[1][0]=r[2]; bl[1][1]=r[3];
                    bl[2][0]=s[0]; bl[2][1]=s[1]; bl[3][0]=s[2]; bl[3][1]=s[3];
                }
#pragma unroll
                for (int nfl = 0; nfl < 4; ++nfl) {
                    const int g = hb*4 + nfl;
                    mma_bf16(acc[0][g], ah0, bh[nfl]);
                    mma_bf16(acc[1][g], ah1, bh[nfl]);
                }
#pragma unroll
                for (int nfl = 0; nfl < 4; ++nfl) {
                    const int g = hb*4 + nfl;
                    mma_bf16(acc[0][g], al0, bh[nfl]);
                    mma_bf16(acc[1][g], al1, bh[nfl]);
                }
#pragma unroll
                for (int nfl = 0; nfl < 4; ++nfl) {
                    const int g = hb*4 + nfl;
                    mma_bf16(acc[0][g], ah0, bl[nfl]);
                    mma_bf16(acc[1][g], ah1, bl[nfl]);
                }
            }
        }

        // ---- epilogue (no syncs, no smem)
        if (LAYER == 0) {
            const int s0 = tIdx * 128;
            const int rb = wr*32 + (lane >> 2);
#pragma unroll
            for (int nf = 0; nf < 8; ++nf) {
                const int c0 = wc*64 + nf*8 + (lane & 3)*2;
                float* p0 = g_y1 + (size_t)c0*NSAMP + s0;
                float* p1 = g_y1 + (size_t)(c0+1)*NSAMP + s0;
#pragma unroll
                for (int mi = 0; mi < 2; ++mi) {
                    const int r = rb + mi*16;
                    const float a0 = acc[mi][nf][0], a1 = acc[mi][nf][1];
                    const float a2 = acc[mi][nf][2], a3 = acc[mi][nf][3];
                    p0[r]     = a0;  p1[r]     = a1;
                    p0[r + 8] = a2;  p1[r + 8] = a3;
                    fsum[nf*2]   += a0 + a2;  fsq[nf*2]   += a0*a0 + a2*a2;
                    fsum[nf*2+1] += a1 + a3;  fsq[nf*2+1] += a1*a1 + a3*a3;
                }
            }
        } else {
            const int b = tIdx / TPB;
            const int n = (tIdx % TPB)*4 + wr;
            float* poolp = g_pool + ((size_t)(b*NPTS + n))*CC;
#pragma unroll
            for (int nf = 0; nf < 8; ++nf) {
#pragma unroll
                for (int e = 0; e < 2; ++e) {
                    const float v0 = acc[0][nf][e],   v1 = acc[0][nf][e+2];
                    const float v2 = acc[1][nf][e],   v3 = acc[1][nf][e+2];
                    fsum[nf*2+e] += v0 + v1 + v2 + v3;
                    fsq[nf*2+e]  += v0*v0 + v1*v1 + v2*v2 + v3*v3;
                    float mx = fmaxf(fmaxf(v0, v1), fmaxf(v2, v3));
                    mx = fmaxf(mx, __shfl_xor_sync(FULL, mx, 4));
                    mx = fmaxf(mx, __shfl_xor_sync(FULL, mx, 8));
                    mx = fmaxf(mx, __shfl_xor_sync(FULL, mx, 16));
                    if (lane < 4) poolp[wc*64 + nf*8 + lane*2 + e] = mx;
                }
            }
        }

        tIdx = tNext;
    }

    // ---- CTA-end stats reduction (once)
    const int sbase = (LAYER == 0) ? 0 : 256;
#pragma unroll
    for (int j = 0; j < 16; ++j) {
        float s = fsum[j], q = fsq[j];
        s += __shfl_xor_sync(FULL, s, 4);  q += __shfl_xor_sync(FULL, q, 4);
        s += __shfl_xor_sync(FULL, s, 8);  q += __shfl_xor_sync(FULL, q, 8);
        s += __shfl_xor_sync(FULL, s, 16); q += __shfl_xor_sync(FULL, q, 16);
        if (lane < 4) {
            const int c = wc*64 + (j >> 1)*8 + lane*2 + (j & 1);
            atomicAdd(&g_stat[sbase + c], s);
            atomicAdd(&g_stat[sbase + 128 + c], q);
        }
    }
}

// ------------------------- 4/6: BN stats finalize -------------------------
__global__ void finalize_kernel(const float* __restrict__ g, const float* __restrict__ bp, int layer)
{
    const int c = threadIdx.x;
    const float inv = 1.0f / (float)NSAMP;
    const float mean = g_stat[layer*256 + c] * inv;
    const float var  = g_stat[layer*256 + 128 + c] * inv - mean*mean;
    const float rs = rsqrtf(var + EPSV);
    const float sc = g[c] * rs;
    g_scale[layer*128 + c] = sc;
    g_shift[layer*128 + c] = bp[c] - mean * sc;
}

// ------------------------- 7: bn2 + relu + transpose (b,n,c) -> (b,c,n) -------------------------
// scale > 0 (g=1): bn commutes with max; relu(max) == max(relu)
__global__ __launch_bounds__(256) void final_kernel(float* __restrict__ out)
{
    __shared__ float tile[32][33];
    const int b = blockIdx.x, n0 = blockIdx.y * 32, c0 = blockIdx.z * 32;
    const int t = threadIdx.x;
    const int cl = t & 31, rl = t >> 5;
#pragma unroll
    for (int i = 0; i < 4; ++i) {
        const int n = n0 + rl + i*8;
        tile[rl + i*8][cl] = (n < NPTS) ? g_pool[((size_t)b*NPTS + n)*CC + c0 + cl] : 0.f;
    }
    __syncthreads();
#pragma unroll
    for (int i = 0; i < 4; ++i) {
        const int c = c0 + rl + i*8;
        const int n = n0 + cl;
        if (n < NPTS) {
            const float v = tile[cl][rl + i*8];
            out[((size_t)b*CC + c)*NPTS + n] = fmaxf(fmaf(v, g_scale[128 + c], g_shift[128 + c]), 0.f);
        }
    }
}

// ------------------------- launch -------------------------
extern "C" void kernel_launch(void* const* d_in, const int* in_sizes, int n_in,
                              void* d_out, int out_size)
{
    const float* x      = (const float*)d_in[0];
    const float* coords = (const float*)d_in[1];
    const float* w1     = (const float*)d_in[2];
    const float* g1     = (const float*)d_in[3];
    const float* b1     = (const float*)d_in[4];
    const float* w2     = (const float*)d_in[5];
    const float* g2     = (const float*)d_in[6];
    const float* b2     = (const float*)d_in[7];
    float* out = (float*)d_out;

    cudaFuncSetAttribute(gemm_mma<0>, cudaFuncAttributeMaxDynamicSharedMemorySize, SMEM_P);
    cudaFuncSetAttribute(gemm_mma<1>, cudaFuncAttributeMaxDynamicSharedMemorySize, SMEM_P);

    zero_stats_kernel<<<1, 128>>>();
    transpose_kernel<<<dim3(NB, (NPTS + 15)/16), 256>>>(x);
    knn_kernel<<<dim3(NB, (NPTS + 7)/8), 256>>>(coords);
    gemm_mma<0><<<GRIDP, 256, SMEM_P>>>(w1);
    finalize_kernel<<<1, 128>>>(g1, b1, 0);
    gemm_mma<1><<<GRIDP, 256, SMEM_P>>>(w2);
    finalize_kernel<<<1, 128>>>(g2, b2, 1);
    final_kernel<<<dim3(NB, (NPTS + 31)/32, CC/32), 256>>>(out);
}

// round 14
// speedup vs baseline: 1.1039x; 1.1039x over previous
#include <cuda_runtime.h>
#include <cuda_bf16.h>
#include <cstdint>
#include <math.h>

#define NB    16
#define NPTS  1620
#define KNN_K 32
#define DD    64
#define CC    128
#define NSAMP (NB*NPTS*KNN_K)       // 829440 = 6480 tiles of 128
#define NTILE (NSAMP/128)           // 6480
#define TPB   405                   // tiles per batch
#define EPSV  1e-5f
#define GRIDP 148                   // persistent CTAs, 1 per SM

#define RSB    272                  // bf16 tile row stride bytes (136 elems: 128 + 8 pad)
#define TILE_B (128*RSB)            // 34816 B per 128x128 bf16 tile
// smem: [Bhi][Blo][A0hi][A0lo][A1hi][A1lo][bn 1KB]
#define OFF_BN  (6*TILE_B)
#define SMEM_P  (6*TILE_B + 1024)   // 209920 B

// ------------------------- scratch (static device globals) -------------------------
__device__ __align__(16) float g_featsT[NB*NPTS*DD];       // (b,n,d)
__device__ int   g_idx[NB*NPTS*KNN_K];
__device__ __align__(16) float g_y1[(size_t)NSAMP*CC];     // channel-major y1[c*NSAMP + s]
__device__ __align__(16) float g_pool[(size_t)NB*NPTS*CC]; // raw max over k, (b,n,c)
__device__ float g_stat[512];                              // [sum1|sq1|sum2|sq2] x 128
__device__ float g_scale[256];
__device__ float g_shift[256];

// ------------------------- helpers -------------------------
__device__ __forceinline__ uint32_t smem_u32(const void* p) {
    uint32_t a; asm("{ .reg .u64 t; cvta.to.shared.u64 t, %1; cvt.u32.u64 %0, t; }" : "=r"(a) : "l"(p));
    return a;
}
__device__ __forceinline__ void ldsm_x4(uint32_t* r, uint32_t addr) {
    asm volatile("ldmatrix.sync.aligned.m8n8.x4.shared.b16 {%0,%1,%2,%3}, [%4];"
        : "=r"(r[0]), "=r"(r[1]), "=r"(r[2]), "=r"(r[3]) : "r"(addr));
}
__device__ __forceinline__ void mma_bf16(float* c, const uint32_t* a, const uint32_t* b) {
    asm volatile("mma.sync.aligned.m16n8k16.row.col.f32.bf16.bf16.f32 "
        "{%0,%1,%2,%3}, {%4,%5,%6,%7}, {%8,%9}, {%0,%1,%2,%3};"
        : "+f"(c[0]), "+f"(c[1]), "+f"(c[2]), "+f"(c[3])
        : "r"(a[0]), "r"(a[1]), "r"(a[2]), "r"(a[3]), "r"(b[0]), "r"(b[1]));
}
__device__ __forceinline__ uint32_t pack2(__nv_bfloat16 a, __nv_bfloat16 b) {
    return ((uint32_t)__bfloat16_as_ushort(b) << 16) | (uint32_t)__bfloat16_as_ushort(a);
}
// split 4 fp32 into bf16 hi + bf16 residual-lo; store 8B each (col local 0..127)
__device__ __forceinline__ void store_hl4(char* hiP, char* loP, int row, int col, float4 v) {
    const int off = row*RSB + col*2;
    const __nv_bfloat16 bx = __float2bfloat16(v.x), by = __float2bfloat16(v.y);
    const __nv_bfloat16 bz = __float2bfloat16(v.z), bw = __float2bfloat16(v.w);
    uint2 hh; hh.x = pack2(bx, by); hh.y = pack2(bz, bw);
    *(uint2*)(hiP + off) = hh;
    const __nv_bfloat16 lx = __float2bfloat16(v.x - __bfloat162float(bx));
    const __nv_bfloat16 ly = __float2bfloat16(v.y - __bfloat162float(by));
    const __nv_bfloat16 lz = __float2bfloat16(v.z - __bfloat162float(bz));
    const __nv_bfloat16 lw = __float2bfloat16(v.w - __bfloat162float(bw));
    uint2 ll; ll.x = pack2(lx, ly); ll.y = pack2(lz, lw);
    *(uint2*)(loP + off) = ll;
}

// ------------------------- 0: zero stats -------------------------
__global__ void zero_stats_kernel() {
    const int t = threadIdx.x;
#pragma unroll
    for (int i = 0; i < 4; ++i) g_stat[t + 128*i] = 0.f;
}

// ------------------------- 1: transpose x (B,D,N) -> featsT (B,N,D) -------------------------
__global__ __launch_bounds__(256) void transpose_kernel(const float* __restrict__ x)
{
    __shared__ float tile[16][DD + 1];
    const int b = blockIdx.x, n0 = blockIdx.y * 16;
    const int t = threadIdx.x;
    const int nn = t & 15, dbq = t >> 4;
#pragma unroll
    for (int i = 0; i < 4; ++i) {
        const int d = i*16 + dbq;
        const int n = n0 + nn;
        tile[nn][d] = (n < NPTS) ? x[((size_t)b*DD + d)*NPTS + n] : 0.f;
    }
    __syncthreads();
    const int d2 = t & 63, nb2 = t >> 6;
#pragma unroll
    for (int i = 0; i < 4; ++i) {
        const int nn2 = nb2 + i*4;
        const int n = n0 + nn2;
        if (n < NPTS) g_featsT[((size_t)b*NPTS + n)*DD + d2] = tile[nn2][d2];
    }
}

// ------------------------- 2: KNN warp-bitonic top-32 -------------------------
__device__ __forceinline__ void cmpswap_lex(float& d, int& i, int j, bool up) {
    const unsigned FULL = 0xffffffffu;
    const float od = __shfl_xor_sync(FULL, d, j);
    const int   oi = __shfl_xor_sync(FULL, i, j);
    const bool lower = ((threadIdx.x & j) == 0);
    const bool selfS = (d < od) || (d == od && i < oi);
    if (selfS != (lower == up)) { d = od; i = oi; }
}
__global__ __launch_bounds__(256) void knn_kernel(const float* __restrict__ coords)
{
    __shared__ float4 spts[NPTS];
    const unsigned FULL = 0xffffffffu;
    const int b = blockIdx.x, t = threadIdx.x;
    for (int i = t; i < NPTS; i += 256) {
        const float* cp = coords + (size_t)(b*NPTS + i)*3;
        const float px = cp[0], py = cp[1], pz = cp[2];
        spts[i] = make_float4(px, py, pz, px*px + py*py + pz*pz);
    }
    __syncthreads();
    const int warp = t >> 5, lane = t & 31;
    const int q = blockIdx.y * 8 + warp;
    if (q >= NPTS) return;
    const float4 me = spts[q];
    float kd = 3.4e38f;
    int   ki = (1 << 30) + lane;
    for (int m0 = 0; m0 < NPTS; m0 += 32) {
        const int m = m0 + lane;
        float d; int mi;
        if (m < NPTS) {
            const float4 o = spts[m];
            d = me.w + o.w - 2.f*(me.x*o.x + me.y*o.y + me.z*o.z);
            mi = m;
        } else { d = 3.4e38f; mi = (1 << 30) + lane; }
        const float thr  = __shfl_sync(FULL, kd, 31);
        const int   thrI = __shfl_sync(FULL, ki, 31);
        const bool better = (d < thr) || (d == thr && mi < thrI);
        if (__any_sync(FULL, better)) {
#pragma unroll
            for (int k = 2; k <= 32; k <<= 1) {
                const bool up = ((lane & k) == 0);
#pragma unroll
                for (int j = k >> 1; j >= 1; j >>= 1) cmpswap_lex(d, mi, j, up);
            }
            d  = __shfl_xor_sync(FULL, d, 31);
            mi = __shfl_xor_sync(FULL, mi, 31);
            const bool keepS = (kd < d) || (kd == d && ki < mi);
            float nd = keepS ? kd : d;
            int   ni = keepS ? ki : mi;
#pragma unroll
            for (int j = 16; j >= 1; j >>= 1) cmpswap_lex(nd, ni, j, true);
            kd = nd; ki = ni;
        }
    }
    g_idx[((size_t)b*NPTS + q)*KNN_K + lane] = ki;
}

// ------------------------- 3/5: persistent bf16x3 mma.sync GEMM, 512 threads -------------------------
// 16 warps: (wid&3)=wr rows wr*32..+31, (wid>>2)=wc cols wc*32..+31. B resident;
// A double-buffered; register prefetch of next tile under current mma.
template<int LAYER>
__global__ __launch_bounds__(512, 1) void gemm_mma(const float* __restrict__ W)
{
    extern __shared__ char sb[];
    char* sBhi = sb;
    char* sBlo = sb + TILE_B;
    float* sBN = (float*)(sb + OFF_BN);
    const int t = threadIdx.x, wid = t >> 5, lane = t & 31;
    const unsigned FULL = 0xffffffffu;
    const uint32_t base = smem_u32(sb);
    const int wr = wid & 3, wc = wid >> 2;
    const uint32_t arow = (uint32_t)((wr*32 + (lane & 15))*RSB + ((lane >> 4) * 8) * 2);
    const uint32_t brow = (uint32_t)((wc*32 + (lane & 7) + ((lane >> 4) << 3))*RSB + (((lane >> 3) & 1) * 8) * 2);
    const int sA = t >> 2, q4 = t & 3;   // 4 threads per row, quarter q4

    // ---- one-time: B tile (W hi/lo, full K=128) + bn params
    {
        const int o = t >> 2;
        const float4* wrow = (const float4*)(W + (size_t)o*CC + q4*32);
#pragma unroll
        for (int j = 0; j < 8; ++j)
            store_hl4(sBhi, sBlo, o, q4*32 + j*4, wrow[j]);
    }
    if (LAYER == 1 && t < 128) { sBN[t] = g_scale[t]; sBN[128 + t] = g_shift[t]; }

    float fsum[8], fsq[8];
#pragma unroll
    for (int j = 0; j < 8; ++j) { fsum[j] = 0.f; fsq[j] = 0.f; }

    float4 pre[8];
    int tIdx = blockIdx.x;

    // ---- prologue prefetch of first tile
    if (tIdx < NTILE) {
        if (LAYER == 0) {
            const int b = tIdx / TPB, r0 = (tIdx % TPB) * 128;
            const int n  = r0 / KNN_K + (sA >> 5);
            const int kk = sA & 31;
            const int nbr = g_idx[((size_t)b*NPTS + n)*KNN_K + kk];
            const float4* nrow = (const float4*)(g_featsT + (size_t)(b*NPTS + nbr)*DD) + q4*4;
            const float4* crow = (const float4*)(g_featsT + (size_t)(b*NPTS + n)*DD) + q4*4;
#pragma unroll
            for (int j = 0; j < 4; ++j) { pre[j] = nrow[j]; pre[4+j] = crow[j]; }
        } else {
            const int s0 = tIdx * 128;
#pragma unroll
            for (int i = 0; i < 2; ++i) {
                const int cb = (wid + i*16) * 4;
                const float* p0 = g_y1 + (size_t)(cb+0)*NSAMP + s0;
                const float* p1 = g_y1 + (size_t)(cb+1)*NSAMP + s0;
                const float* p2 = g_y1 + (size_t)(cb+2)*NSAMP + s0;
                const float* p3 = g_y1 + (size_t)(cb+3)*NSAMP + s0;
#pragma unroll
                for (int p = 0; p < 4; ++p) {
                    const int row = p*32 + lane;
                    pre[i*4+p] = make_float4(p0[row], p1[row], p2[row], p3[row]);
                }
            }
        }
    }
    __syncthreads();   // B + bn ready

    int buf = 0;
    while (tIdx < NTILE) {
        char* sAhi = sb + (2 + 2*buf)*TILE_B;
        char* sAlo = sAhi + TILE_B;

        // ---- convert + STS current tile from regs
        if (LAYER == 0) {
#pragma unroll
            for (int j = 0; j < 4; ++j) {
                const float4 nv = pre[j], cv = pre[4+j];
                float4 d; d.x = nv.x-cv.x; d.y = nv.y-cv.y; d.z = nv.z-cv.z; d.w = nv.w-cv.w;
                const int dcol = q4*16 + j*4;
                store_hl4(sAhi, sAlo, sA, dcol, d);         // diff features cols 0..63
                store_hl4(sAhi, sAlo, sA, 64 + dcol, cv);   // center features cols 64..127
            }
        } else {
#pragma unroll
            for (int i = 0; i < 2; ++i) {
                const int cb = (wid + i*16) * 4;
                const float s0c = sBN[cb+0], h0 = sBN[128+cb+0];
                const float s1c = sBN[cb+1], h1 = sBN[128+cb+1];
                const float s2c = sBN[cb+2], h2 = sBN[128+cb+2];
                const float s3c = sBN[cb+3], h3 = sBN[128+cb+3];
#pragma unroll
                for (int p = 0; p < 4; ++p) {
                    const int row = p*32 + lane;
                    const float4 u = pre[i*4+p];
                    float4 v;
                    v.x = fmaxf(fmaf(u.x, s0c, h0), 0.f);
                    v.y = fmaxf(fmaf(u.y, s1c, h1), 0.f);
                    v.z = fmaxf(fmaf(u.z, s2c, h2), 0.f);
                    v.w = fmaxf(fmaf(u.w, s3c, h3), 0.f);
                    store_hl4(sAhi, sAlo, row, cb, v);
                }
            }
        }
        __syncthreads();   // A(t) ready; other buffer free

        // ---- prefetch next tile into regs (latency hides under mma)
        const int tNext = tIdx + GRIDP;
        if (tNext < NTILE) {
            if (LAYER == 0) {
                const int b = tNext / TPB, r0 = (tNext % TPB) * 128;
                const int n  = r0 / KNN_K + (sA >> 5);
                const int kk = sA & 31;
                const int nbr = g_idx[((size_t)b*NPTS + n)*KNN_K + kk];
                const float4* nrow = (const float4*)(g_featsT + (size_t)(b*NPTS + nbr)*DD) + q4*4;
                const float4* crow = (const float4*)(g_featsT + (size_t)(b*NPTS + n)*DD) + q4*4;
#pragma unroll
                for (int j = 0; j < 4; ++j) { pre[j] = nrow[j]; pre[4+j] = crow[j]; }
            } else {
                const int s0 = tNext * 128;
#pragma unroll
                for (int i = 0; i < 2; ++i) {
                    const int cb = (wid + i*16) * 4;
                    const float* p0 = g_y1 + (size_t)(cb+0)*NSAMP + s0;
                    const float* p1 = g_y1 + (size_t)(cb+1)*NSAMP + s0;
                    const float* p2 = g_y1 + (size_t)(cb+2)*NSAMP + s0;
                    const float* p3 = g_y1 + (size_t)(cb+3)*NSAMP + s0;
#pragma unroll
                    for (int p = 0; p < 4; ++p) {
                        const int row = p*32 + lane;
                        pre[i*4+p] = make_float4(p0[row], p1[row], p2[row], p3[row]);
                    }
                }
            }
        }

        // ---- mma mainloop: fused 3 products, 8 k-steps, 32x32 warp tile
        float acc[2][4][4];
#pragma unroll
        for (int mi = 0; mi < 2; ++mi)
#pragma unroll
            for (int nf = 0; nf < 4; ++nf)
#pragma unroll
                for (int e = 0; e < 4; ++e) acc[mi][nf][e] = 0.f;

        const uint32_t aHp = base + (uint32_t)((2 + 2*buf)*TILE_B) + arow;
        const uint32_t aLp = aHp + (uint32_t)TILE_B;
        const uint32_t bHp = base + brow;
        const uint32_t bLp = bHp + (uint32_t)TILE_B;
#pragma unroll
        for (int ks = 0; ks < 8; ++ks) {
            const uint32_t ko = (uint32_t)(ks * 32);
            uint32_t ah0[4], ah1[4], al0[4], al1[4];
            ldsm_x4(ah0, aHp + ko);
            ldsm_x4(ah1, aHp + 16*RSB + ko);
            ldsm_x4(al0, aLp + ko);
            ldsm_x4(al1, aLp + 16*RSB + ko);
            uint32_t bh[4][2], bl[4][2];
            {
                uint32_t r[4], s[4];
                ldsm_x4(r, bHp + ko);
                ldsm_x4(s, bHp + 16*RSB + ko);
                bh[0][0]=r[0]; bh[0][1]=r[1]; bh[1][0]=r[2]; bh[1][1]=r[3];
                bh[2][0]=s[0]; bh[2][1]=s[1]; bh[3][0]=s[2]; bh[3][1]=s[3];
                ldsm_x4(r, bLp + ko);
                ldsm_x4(s, bLp + 16*RSB + ko);
                bl[0][0]=r[0]; bl[0][1]=r[1]; bl[1][0]=r[2]; bl[1][1]=r[3];
                bl[2][0]=s[0]; bl[2][1]=s[1]; bl[3][0]=s[2]; bl[3][1]=s[3];
            }
#pragma unroll
            for (int nf = 0; nf < 4; ++nf) {
                mma_bf16(acc[0][nf], ah0, bh[nf]);
                mma_bf16(acc[1][nf], ah1, bh[nf]);
            }
#pragma unroll
            for (int nf = 0; nf < 4; ++nf) {
                mma_bf16(acc[0][nf], al0, bh[nf]);
                mma_bf16(acc[1][nf], al1, bh[nf]);
            }
#pragma unroll
            for (int nf = 0; nf < 4; ++nf) {
                mma_bf16(acc[0][nf], ah0, bl[nf]);
                mma_bf16(acc[1][nf], ah1, bl[nf]);
            }
        }

        // ---- epilogue (no syncs, no smem)
        if (LAYER == 0) {
            const int s0 = tIdx * 128;
            const int rb = wr*32 + (lane >> 2);
#pragma unroll
            for (int nf = 0; nf < 4; ++nf) {
                const int c0 = wc*32 + nf*8 + (lane & 3)*2;
                float* p0 = g_y1 + (size_t)c0*NSAMP + s0;
                float* p1 = g_y1 + (size_t)(c0+1)*NSAMP + s0;
#pragma unroll
                for (int mi = 0; mi < 2; ++mi) {
                    const int r = rb + mi*16;
                    const float a0 = acc[mi][nf][0], a1 = acc[mi][nf][1];
                    const float a2 = acc[mi][nf][2], a3 = acc[mi][nf][3];
                    p0[r]     = a0;  p1[r]     = a1;
                    p0[r + 8] = a2;  p1[r + 8] = a3;
                    fsum[nf*2]   += a0 + a2;  fsq[nf*2]   += a0*a0 + a2*a2;
                    fsum[nf*2+1] += a1 + a3;  fsq[nf*2+1] += a1*a1 + a3*a3;
                }
            }
        } else {
            const int b = tIdx / TPB;
            const int n = (tIdx % TPB)*4 + wr;
            float* poolp = g_pool + ((size_t)(b*NPTS + n))*CC;
#pragma unroll
            for (int nf = 0; nf < 4; ++nf) {
#pragma unroll
                for (int e = 0; e < 2; ++e) {
                    const float v0 = acc[0][nf][e],   v1 = acc[0][nf][e+2];
                    const float v2 = acc[1][nf][e],   v3 = acc[1][nf][e+2];
                    fsum[nf*2+e] += v0 + v1 + v2 + v3;
                    fsq[nf*2+e]  += v0*v0 + v1*v1 + v2*v2 + v3*v3;
                    float mx = fmaxf(fmaxf(v0, v1), fmaxf(v2, v3));
                    mx = fmaxf(mx, __shfl_xor_sync(FULL, mx, 4));
                    mx = fmaxf(mx, __shfl_xor_sync(FULL, mx, 8));
                    mx = fmaxf(mx, __shfl_xor_sync(FULL, mx, 16));
                    if (lane < 4) poolp[wc*32 + nf*8 + lane*2 + e] = mx;
                }
            }
        }

        buf ^= 1;
        tIdx = tNext;
    }

    // ---- CTA-end stats reduction (once)
    const int sbase = (LAYER == 0) ? 0 : 256;
#pragma unroll
    for (int j = 0; j < 8; ++j) {
        float s = fsum[j], q = fsq[j];
        s += __shfl_xor_sync(FULL, s, 4);  q += __shfl_xor_sync(FULL, q, 4);
        s += __shfl_xor_sync(FULL, s, 8);  q += __shfl_xor_sync(FULL, q, 8);
        s += __shfl_xor_sync(FULL, s, 16); q += __shfl_xor_sync(FULL, q, 16);
        if (lane < 4) {
            const int c = wc*32 + (j >> 1)*8 + lane*2 + (j & 1);
            atomicAdd(&g_stat[sbase + c], s);
            atomicAdd(&g_stat[sbase + 128 + c], q);
        }
    }
}

// ------------------------- 4/6: BN stats finalize -------------------------
__global__ void finalize_kernel(const float* __restrict__ g, const float* __restrict__ bp, int layer)
{
    const int c = threadIdx.x;
    const float inv = 1.0f / (float)NSAMP;
    const float mean = g_stat[layer*256 + c] * inv;
    const float var  = g_stat[layer*256 + 128 + c] * inv - mean*mean;
    const float rs = rsqrtf(var + EPSV);
    const float sc = g[c] * rs;
    g_scale[layer*128 + c] = sc;
    g_shift[layer*128 + c] = bp[c] - mean * sc;
}

// ------------------------- 7: bn2 + relu + transpose (b,n,c) -> (b,c,n) -------------------------
// scale > 0 (g=1): bn commutes with max; relu(max) == max(relu)
__global__ __launch_bounds__(256) void final_kernel(float* __restrict__ out)
{
    __shared__ float tile[32][33];
    const int b = blockIdx.x, n0 = blockIdx.y * 32, c0 = blockIdx.z * 32;
    const int t = threadIdx.x;
    const int cl = t & 31, rl = t >> 5;
#pragma unroll
    for (int i = 0; i < 4; ++i) {
        const int n = n0 + rl + i*8;
        tile[rl + i*8][cl] = (n < NPTS) ? g_pool[((size_t)b*NPTS + n)*CC + c0 + cl] : 0.f;
    }
    __syncthreads();
#pragma unroll
    for (int i = 0; i < 4; ++i) {
        const int c = c0 + rl + i*8;
        const int n = n0 + cl;
        if (n < NPTS) {
            const float v = tile[cl][rl + i*8];
            out[((size_t)b*CC + c)*NPTS + n] = fmaxf(fmaf(v, g_scale[128 + c], g_shift[128 + c]), 0.f);
        }
    }
}

// ------------------------- launch -------------------------
extern "C" void kernel_launch(void* const* d_in, const int* in_sizes, int n_in,
                              void* d_out, int out_size)
{
    const float* x      = (const float*)d_in[0];
    const float* coords = (const float*)d_in[1];
    const float* w1     = (const float*)d_in[2];
    const float* g1     = (const float*)d_in[3];
    const float* b1     = (const float*)d_in[4];
    const float* w2     = (const float*)d_in[5];
    const float* g2     = (const float*)d_in[6];
    const float* b2     = (const float*)d_in[7];
    float* out = (float*)d_out;

    cudaFuncSetAttribute(gemm_mma<0>, cudaFuncAttributeMaxDynamicSharedMemorySize, SMEM_P);
    cudaFuncSetAttribute(gemm_mma<1>, cudaFuncAttributeMaxDynamicSharedMemorySize, SMEM_P);

    zero_stats_kernel<<<1, 128>>>();
    transpose_kernel<<<dim3(NB, (NPTS + 15)/16), 256>>>(x);
    knn_kernel<<<dim3(NB, (NPTS + 7)/8), 256>>>(coords);
    gemm_mma<0><<<GRIDP, 512, SMEM_P>>>(w1);
    finalize_kernel<<<1, 128>>>(g1, b1, 0);
    gemm_mma<1><<<GRIDP, 512, SMEM_P>>>(w2);
    finalize_kernel<<<1, 128>>>(g2, b2, 1);
    final_kernel<<<dim3(NB, (NPTS + 31)/32, CC/32), 256>>>(out);
}

// round 17
// speedup vs baseline: 1.4046x; 1.2724x over previous
#include <cuda_runtime.h>
#include <cuda_bf16.h>
#include <cstdint>
#include <math.h>

#define NB    16
#define NPTS  1620
#define KNN_K 32
#define DD    64
#define CC    128
#define NSAMP (NB*NPTS*KNN_K)       // 829440 = 6480 tiles of 128
#define NTILE (NSAMP/128)           // 6480
#define TPB   405                   // tiles per batch
#define EPSV  1e-5f
#define GRIDP 148                   // persistent CTAs, 1 per SM

#define RSB    272                  // bf16 tile row stride bytes (136 elems: 128 + 8 pad)
#define TILE_B (128*RSB)            // 34816 B per 128x128 bf16 tile
// smem: [Bhi][Blo][A0hi][A0lo][A1hi][A1lo][bn 1KB]
#define OFF_BN  (6*TILE_B)
#define SMEM_P  (6*TILE_B + 1024)   // 209920 B

// ------------------------- scratch (static device globals) -------------------------
__device__ __align__(16) float g_featsT[NB*NPTS*DD];       // (b,n,d)
__device__ int   g_idx[NB*NPTS*KNN_K];
__device__ __align__(16) float g_y1[(size_t)NSAMP*CC];     // channel-major y1[c*NSAMP + s]
__device__ __align__(16) float g_pool[(size_t)NB*NPTS*CC]; // raw max over k, (b,n,c)
__device__ float g_stat[512];                              // [sum1|sq1|sum2|sq2] x 128
__device__ float g_scale[256];
__device__ float g_shift[256];

// ------------------------- helpers -------------------------
__device__ __forceinline__ uint32_t smem_u32(const void* p) {
    uint32_t a; asm("{ .reg .u64 t; cvta.to.shared.u64 t, %1; cvt.u32.u64 %0, t; }" : "=r"(a) : "l"(p));
    return a;
}
__device__ __forceinline__ void ldsm_x4(uint32_t* r, uint32_t addr) {
    asm volatile("ldmatrix.sync.aligned.m8n8.x4.shared.b16 {%0,%1,%2,%3}, [%4];"
        : "=r"(r[0]), "=r"(r[1]), "=r"(r[2]), "=r"(r[3]) : "r"(addr));
}
__device__ __forceinline__ void mma_bf16(float* c, const uint32_t* a, const uint32_t* b) {
    asm volatile("mma.sync.aligned.m16n8k16.row.col.f32.bf16.bf16.f32 "
        "{%0,%1,%2,%3}, {%4,%5,%6,%7}, {%8,%9}, {%0,%1,%2,%3};"
        : "+f"(c[0]), "+f"(c[1]), "+f"(c[2]), "+f"(c[3])
        : "r"(a[0]), "r"(a[1]), "r"(a[2]), "r"(a[3]), "r"(b[0]), "r"(b[1]));
}
__device__ __forceinline__ uint32_t pack2(__nv_bfloat16 a, __nv_bfloat16 b) {
    return ((uint32_t)__bfloat16_as_ushort(b) << 16) | (uint32_t)__bfloat16_as_ushort(a);
}
// split 4 fp32 into bf16 hi + bf16 residual-lo; store 8B each (col local 0..127)
__device__ __forceinline__ void store_hl4(char* hiP, char* loP, int row, int col, float4 v) {
    const int off = row*RSB + col*2;
    const __nv_bfloat16 bx = __float2bfloat16(v.x), by = __float2bfloat16(v.y);
    const __nv_bfloat16 bz = __float2bfloat16(v.z), bw = __float2bfloat16(v.w);
    uint2 hh; hh.x = pack2(bx, by); hh.y = pack2(bz, bw);
    *(uint2*)(hiP + off) = hh;
    const __nv_bfloat16 lx = __float2bfloat16(v.x - __bfloat162float(bx));
    const __nv_bfloat16 ly = __float2bfloat16(v.y - __bfloat162float(by));
    const __nv_bfloat16 lz = __float2bfloat16(v.z - __bfloat162float(bz));
    const __nv_bfloat16 lw = __float2bfloat16(v.w - __bfloat162float(bw));
    uint2 ll; ll.x = pack2(lx, ly); ll.y = pack2(lz, lw);
    *(uint2*)(loP + off) = ll;
}

// ------------------------- 0: zero stats -------------------------
__global__ void zero_stats_kernel() {
    const int t = threadIdx.x;
#pragma unroll
    for (int i = 0; i < 4; ++i) g_stat[t + 128*i] = 0.f;
}

// ------------------------- 1: transpose x (B,D,N) -> featsT (B,N,D) -------------------------
__global__ __launch_bounds__(256) void transpose_kernel(const float* __restrict__ x)
{
    __shared__ float tile[16][DD + 1];
    const int b = blockIdx.x, n0 = blockIdx.y * 16;
    const int t = threadIdx.x;
    const int nn = t & 15, dbq = t >> 4;
#pragma unroll
    for (int i = 0; i < 4; ++i) {
        const int d = i*16 + dbq;
        const int n = n0 + nn;
        tile[nn][d] = (n < NPTS) ? x[((size_t)b*DD + d)*NPTS + n] : 0.f;
    }
    __syncthreads();
    const int d2 = t & 63, nb2 = t >> 6;
#pragma unroll
    for (int i = 0; i < 4; ++i) {
        const int nn2 = nb2 + i*4;
        const int n = n0 + nn2;
        if (n < NPTS) g_featsT[((size_t)b*NPTS + n)*DD + d2] = tile[nn2][d2];
    }
}

// ------------------------- 2: KNN warp top-32 (bitonic heavy path + ballot insertion light path) -------------------------
__device__ __forceinline__ void cmpswap_lex(float& d, int& i, int j, bool up) {
    const unsigned FULL = 0xffffffffu;
    const float od = __shfl_xor_sync(FULL, d, j);
    const int   oi = __shfl_xor_sync(FULL, i, j);
    const bool lower = ((threadIdx.x & j) == 0);
    const bool selfS = (d < od) || (d == od && i < oi);
    if (selfS != (lower == up)) { d = od; i = oi; }
}
__global__ __launch_bounds__(256) void knn_kernel(const float* __restrict__ coords)
{
    __shared__ float4 spts[NPTS];
    const unsigned FULL = 0xffffffffu;
    const int b = blockIdx.x, t = threadIdx.x;
    for (int i = t; i < NPTS; i += 256) {
        const float* cp = coords + (size_t)(b*NPTS + i)*3;
        const float px = cp[0], py = cp[1], pz = cp[2];
        spts[i] = make_float4(px, py, pz, px*px + py*py + pz*pz);
    }
    __syncthreads();
    const int warp = t >> 5, lane = t & 31;
    const int q = blockIdx.y * 8 + warp;
    if (q >= NPTS) return;
    const float4 me = spts[q];
    // kd/ki: sorted ascending (lex on (d, idx)) across lanes; lane 31 = current worst kept
    float kd = 3.4e38f;
    int   ki = (1 << 30) + lane;
    float thrD = 3.4e38f; int thrI = (1 << 30) + 31;

    for (int m0 = 0; m0 < NPTS; m0 += 32) {
        const int m = m0 + lane;
        float d; int mi;
        if (m < NPTS) {
            const float4 o = spts[m];
            d = me.w + o.w - 2.f*(me.x*o.x + me.y*o.y + me.z*o.z);
            mi = m;
        } else { d = 3.4e38f; mi = (1 << 30) + lane; }

        const bool better = (d < thrD) || (d == thrD && mi < thrI);
        unsigned qmask = __ballot_sync(FULL, better);
        if (qmask == 0) continue;

        if (__popc(qmask) > 8) {
            // ---- heavy path: bitonic sort batch + merge (verified)
#pragma unroll
            for (int k = 2; k <= 32; k <<= 1) {
                const bool up = ((lane & k) == 0);
#pragma unroll
                for (int j = k >> 1; j >= 1; j >>= 1) cmpswap_lex(d, mi, j, up);
            }
            d  = __shfl_xor_sync(FULL, d, 31);
            mi = __shfl_xor_sync(FULL, mi, 31);
            const bool keepS = (kd < d) || (kd == d && ki < mi);
            float nd = keepS ? kd : d;
            int   ni = keepS ? ki : mi;
#pragma unroll
            for (int j = 16; j >= 1; j >>= 1) cmpswap_lex(nd, ni, j, true);
            kd = nd; ki = ni;
        } else {
            // ---- light path: serial ballot-positioned insertion per qualifier
            while (qmask) {
                const int j = __ffs(qmask) - 1;
                qmask &= qmask - 1;
                const float dc = __shfl_sync(FULL, d, j);
                const int   mc = __shfl_sync(FULL, mi, j);
                // re-check vs (possibly tightened) threshold
                const bool ok = (dc < thrD) || (dc == thrD && mc < thrI);
                // all lanes: compute insert position & shifted values
                const bool less = (kd < dc) || (kd == dc && ki < mc);
                const int pos = __popc(__ballot_sync(FULL, less));   // sorted -> prefix
                const float pk = __shfl_up_sync(FULL, kd, 1);
                const int   pi = __shfl_up_sync(FULL, ki, 1);
                if (ok) {
                    if (lane == pos)      { kd = dc; ki = mc; }
                    else if (lane > pos)  { kd = pk; ki = pi; }
                    thrD = __shfl_sync(FULL, kd, 31);
                    thrI = __shfl_sync(FULL, ki, 31);
                }
            }
            continue;   // threshold already updated
        }
        thrD = __shfl_sync(FULL, kd, 31);
        thrI = __shfl_sync(FULL, ki, 31);
    }
    g_idx[((size_t)b*NPTS + q)*KNN_K + lane] = ki;
}

// ------------------------- 3/5: persistent bf16x3 mma.sync GEMM, 512 threads -------------------------
// 16 warps: (wid&3)=wr rows wr*32..+31, (wid>>2)=wc cols wc*32..+31. B resident;
// A double-buffered; register prefetch of next tile under current mma.
template<int LAYER>
__global__ __launch_bounds__(512, 1) void gemm_mma(const float* __restrict__ W)
{
    extern __shared__ char sb[];
    char* sBhi = sb;
    char* sBlo = sb + TILE_B;
    float* sBN = (float*)(sb + OFF_BN);
    const int t = threadIdx.x, wid = t >> 5, lane = t & 31;
    const unsigned FULL = 0xffffffffu;
    const uint32_t base = smem_u32(sb);
    const int wr = wid & 3, wc = wid >> 2;
    const uint32_t arow = (uint32_t)((wr*32 + (lane & 15))*RSB + ((lane >> 4) * 8) * 2);
    const uint32_t brow = (uint32_t)((wc*32 + (lane & 7) + ((lane >> 4) << 3))*RSB + (((lane >> 3) & 1) * 8) * 2);
    const int sA = t >> 2, q4 = t & 3;   // 4 threads per row, quarter q4

    // ---- one-time: B tile (W hi/lo, full K=128) + bn params
    {
        const int o = t >> 2;
        const float4* wrow = (const float4*)(W + (size_t)o*CC + q4*32);
#pragma unroll
        for (int j = 0; j < 8; ++j)
            store_hl4(sBhi, sBlo, o, q4*32 + j*4, wrow[j]);
    }
    if (LAYER == 1 && t < 128) { sBN[t] = g_scale[t]; sBN[128 + t] = g_shift[t]; }

    float fsum[8], fsq[8];
#pragma unroll
    for (int j = 0; j < 8; ++j) { fsum[j] = 0.f; fsq[j] = 0.f; }

    float4 pre[8];
    int tIdx = blockIdx.x;

    // ---- prologue prefetch of first tile
    if (tIdx < NTILE) {
        if (LAYER == 0) {
            const int b = tIdx / TPB, r0 = (tIdx % TPB) * 128;
            const int n  = r0 / KNN_K + (sA >> 5);
            const int kk = sA & 31;
            const int nbr = g_idx[((size_t)b*NPTS + n)*KNN_K + kk];
            const float4* nrow = (const float4*)(g_featsT + (size_t)(b*NPTS + nbr)*DD) + q4*4;
            const float4* crow = (const float4*)(g_featsT + (size_t)(b*NPTS + n)*DD) + q4*4;
#pragma unroll
            for (int j = 0; j < 4; ++j) { pre[j] = nrow[j]; pre[4+j] = crow[j]; }
        } else {
            const int s0 = tIdx * 128;
#pragma unroll
            for (int i = 0; i < 2; ++i) {
                const int cb = (wid + i*16) * 4;
                const float* p0 = g_y1 + (size_t)(cb+0)*NSAMP + s0;
                const float* p1 = g_y1 + (size_t)(cb+1)*NSAMP + s0;
                const float* p2 = g_y1 + (size_t)(cb+2)*NSAMP + s0;
                const float* p3 = g_y1 + (size_t)(cb+3)*NSAMP + s0;
#pragma unroll
                for (int p = 0; p < 4; ++p) {
                    const int row = p*32 + lane;
                    pre[i*4+p] = make_float4(p0[row], p1[row], p2[row], p3[row]);
                }
            }
        }
    }
    __syncthreads();   // B + bn ready

    int buf = 0;
    while (tIdx < NTILE) {
        char* sAhi = sb + (2 + 2*buf)*TILE_B;
        char* sAlo = sAhi + TILE_B;

        // ---- convert + STS current tile from regs
        if (LAYER == 0) {
#pragma unroll
            for (int j = 0; j < 4; ++j) {
                const float4 nv = pre[j], cv = pre[4+j];
                float4 d; d.x = nv.x-cv.x; d.y = nv.y-cv.y; d.z = nv.z-cv.z; d.w = nv.w-cv.w;
                const int dcol = q4*16 + j*4;
                store_hl4(sAhi, sAlo, sA, dcol, d);         // diff features cols 0..63
                store_hl4(sAhi, sAlo, sA, 64 + dcol, cv);   // center features cols 64..127
            }
        } else {
#pragma unroll
            for (int i = 0; i < 2; ++i) {
                const int cb = (wid + i*16) * 4;
                const float s0c = sBN[cb+0], h0 = sBN[128+cb+0];
                const float s1c = sBN[cb+1], h1 = sBN[128+cb+1];
                const float s2c = sBN[cb+2], h2 = sBN[128+cb+2];
                const float s3c = sBN[cb+3], h3 = sBN[128+cb+3];
#pragma unroll
                for (int p = 0; p < 4; ++p) {
                    const int row = p*32 + lane;
                    const float4 u = pre[i*4+p];
                    float4 v;
                    v.x = fmaxf(fmaf(u.x, s0c, h0), 0.f);
                    v.y = fmaxf(fmaf(u.y, s1c, h1), 0.f);
                    v.z = fmaxf(fmaf(u.z, s2c, h2), 0.f);
                    v.w = fmaxf(fmaf(u.w, s3c, h3), 0.f);
                    store_hl4(sAhi, sAlo, row, cb, v);
                }
            }
        }
        __syncthreads();   // A(t) ready; other buffer free

        // ---- prefetch next tile into regs (latency hides under mma)
        const int tNext = tIdx + GRIDP;
        if (tNext < NTILE) {
            if (LAYER == 0) {
                const int b = tNext / TPB, r0 = (tNext % TPB) * 128;
                const int n  = r0 / KNN_K + (sA >> 5);
                const int kk = sA & 31;
                const int nbr = g_idx[((size_t)b*NPTS + n)*KNN_K + kk];
                const float4* nrow = (const float4*)(g_featsT + (size_t)(b*NPTS + nbr)*DD) + q4*4;
                const float4* crow = (const float4*)(g_featsT + (size_t)(b*NPTS + n)*DD) + q4*4;
#pragma unroll
                for (int j = 0; j < 4; ++j) { pre[j] = nrow[j]; pre[4+j] = crow[j]; }
            } else {
                const int s0 = tNext * 128;
#pragma unroll
                for (int i = 0; i < 2; ++i) {
                    const int cb = (wid + i*16) * 4;
                    const float* p0 = g_y1 + (size_t)(cb+0)*NSAMP + s0;
                    const float* p1 = g_y1 + (size_t)(cb+1)*NSAMP + s0;
                    const float* p2 = g_y1 + (size_t)(cb+2)*NSAMP + s0;
                    const float* p3 = g_y1 + (size_t)(cb+3)*NSAMP + s0;
#pragma unroll
                    for (int p = 0; p < 4; ++p) {
                        const int row = p*32 + lane;
                        pre[i*4+p] = make_float4(p0[row], p1[row], p2[row], p3[row]);
                    }
                }
            }
        }

        // ---- mma mainloop: fused 3 products, 8 k-steps, 32x32 warp tile
        float acc[2][4][4];
#pragma unroll
        for (int mi = 0; mi < 2; ++mi)
#pragma unroll
            for (int nf = 0; nf < 4; ++nf)
#pragma unroll
                for (int e = 0; e < 4; ++e) acc[mi][nf][e] = 0.f;

        const uint32_t aHp = base + (uint32_t)((2 + 2*buf)*TILE_B) + arow;
        const uint32_t aLp = aHp + (uint32_t)TILE_B;
        const uint32_t bHp = base + brow;
        const uint32_t bLp = bHp + (uint32_t)TILE_B;
#pragma unroll
        for (int ks = 0; ks < 8; ++ks) {
            const uint32_t ko = (uint32_t)(ks * 32);
            uint32_t ah0[4], ah1[4], al0[4], al1[4];
            ldsm_x4(ah0, aHp + ko);
            ldsm_x4(ah1, aHp + 16*RSB + ko);
            ldsm_x4(al0, aLp + ko);
            ldsm_x4(al1, aLp + 16*RSB + ko);
            uint32_t bh[4][2], bl[4][2];
            {
                uint32_t r[4], s[4];
                ldsm_x4(r, bHp + ko);
                ldsm_x4(s, bHp + 16*RSB + ko);
                bh[0][0]=r[0]; bh[0][1]=r[1]; bh[1][0]=r[2]; bh[1][1]=r[3];
                bh[2][0]=s[0]; bh[2][1]=s[1]; bh[3][0]=s[2]; bh[3][1]=s[3];
                ldsm_x4(r, bLp + ko);
                ldsm_x4(s, bLp + 16*RSB + ko);
                bl[0][0]=r[0]; bl[0][1]=r[1]; bl[1][0]=r[2]; bl[1][1]=r[3];
                bl[2][0]=s[0]; bl[2][1]=s[1]; bl[3][0]=s[2]; bl[3][1]=s[3];
            }
#pragma unroll
            for (int nf = 0; nf < 4; ++nf) {
                mma_bf16(acc[0][nf], ah0, bh[nf]);
                mma_bf16(acc[1][nf], ah1, bh[nf]);
            }
#pragma unroll
            for (int nf = 0; nf < 4; ++nf) {
                mma_bf16(acc[0][nf], al0, bh[nf]);
                mma_bf16(acc[1][nf], al1, bh[nf]);
            }
#pragma unroll
            for (int nf = 0; nf < 4; ++nf) {
                mma_bf16(acc[0][nf], ah0, bl[nf]);
                mma_bf16(acc[1][nf], ah1, bl[nf]);
            }
        }

        // ---- epilogue (no syncs, no smem)
        if (LAYER == 0) {
            const int s0 = tIdx * 128;
            const int rb = wr*32 + (lane >> 2);
#pragma unroll
            for (int nf = 0; nf < 4; ++nf) {
                const int c0 = wc*32 + nf*8 + (lane & 3)*2;
                float* p0 = g_y1 + (size_t)c0*NSAMP + s0;
                float* p1 = g_y1 + (size_t)(c0+1)*NSAMP + s0;
#pragma unroll
                for (int mi = 0; mi < 2; ++mi) {
                    const int r = rb + mi*16;
                    const float a0 = acc[mi][nf][0], a1 = acc[mi][nf][1];
                    const float a2 = acc[mi][nf][2], a3 = acc[mi][nf][3];
                    p0[r]     = a0;  p1[r]     = a1;
                    p0[r + 8] = a2;  p1[r + 8] = a3;
                    fsum[nf*2]   += a0 + a2;  fsq[nf*2]   += a0*a0 + a2*a2;
                    fsum[nf*2+1] += a1 + a3;  fsq[nf*2+1] += a1*a1 + a3*a3;
                }
            }
        } else {
            const int b = tIdx / TPB;
            const int n = (tIdx % TPB)*4 + wr;
            float* poolp = g_pool + ((size_t)(b*NPTS + n))*CC;
#pragma unroll
            for (int nf = 0; nf < 4; ++nf) {
#pragma unroll
                for (int e = 0; e < 2; ++e) {
                    const float v0 = acc[0][nf][e],   v1 = acc[0][nf][e+2];
                    const float v2 = acc[1][nf][e],   v3 = acc[1][nf][e+2];
                    fsum[nf*2+e] += v0 + v1 + v2 + v3;
                    fsq[nf*2+e]  += v0*v0 + v1*v1 + v2*v2 + v3*v3;
                    float mx = fmaxf(fmaxf(v0, v1), fmaxf(v2, v3));
                    mx = fmaxf(mx, __shfl_xor_sync(FULL, mx, 4));
                    mx = fmaxf(mx, __shfl_xor_sync(FULL, mx, 8));
                    mx = fmaxf(mx, __shfl_xor_sync(FULL, mx, 16));
                    if (lane < 4) poolp[wc*32 + nf*8 + lane*2 + e] = mx;
                }
            }
        }

        buf ^= 1;
        tIdx = tNext;
    }

    // ---- CTA-end stats reduction (once)
    const int sbase = (LAYER == 0) ? 0 : 256;
#pragma unroll
    for (int j = 0; j < 8; ++j) {
        float s = fsum[j], q = fsq[j];
        s += __shfl_xor_sync(FULL, s, 4);  q += __shfl_xor_sync(FULL, q, 4);
        s += __shfl_xor_sync(FULL, s, 8);  q += __shfl_xor_sync(FULL, q, 8);
        s += __shfl_xor_sync(FULL, s, 16); q += __shfl_xor_sync(FULL, q, 16);
        if (lane < 4) {
            const int c = wc*32 + (j >> 1)*8 + lane*2 + (j & 1);
            atomicAdd(&g_stat[sbase + c], s);
            atomicAdd(&g_stat[sbase + 128 + c], q);
        }
    }
}

// ------------------------- 4/6: BN stats finalize -------------------------
__global__ void finalize_kernel(const float* __restrict__ g, const float* __restrict__ bp, int layer)
{
    const int c = threadIdx.x;
    const float inv = 1.0f / (float)NSAMP;
    const float mean = g_stat[layer*256 + c] * inv;
    const float var  = g_stat[layer*256 + 128 + c] * inv - mean*mean;
    const float rs = rsqrtf(var + EPSV);
    const float sc = g[c] * rs;
    g_scale[layer*128 + c] = sc;
    g_shift[layer*128 + c] = bp[c] - mean * sc;
}

// ------------------------- 7: bn2 + relu + transpose (b,n,c) -> (b,c,n) -------------------------
// scale > 0 (g=1): bn commutes with max; relu(max) == max(relu)
__global__ __launch_bounds__(256) void final_kernel(float* __restrict__ out)
{
    __shared__ float tile[32][33];
    const int b = blockIdx.x, n0 = blockIdx.y * 32, c0 = blockIdx.z * 32;
    const int t = threadIdx.x;
    const int cl = t & 31, rl = t >> 5;
#pragma unroll
    for (int i = 0; i < 4; ++i) {
        const int n = n0 + rl + i*8;
        tile[rl + i*8][cl] = (n < NPTS) ? g_pool[((size_t)b*NPTS + n)*CC + c0 + cl] : 0.f;
    }
    __syncthreads();
#pragma unroll
    for (int i = 0; i < 4; ++i) {
        const int c = c0 + rl + i*8;
        const int n = n0 + cl;
        if (n < NPTS) {
            const float v = tile[cl][rl + i*8];
            out[((size_t)b*CC + c)*NPTS + n] = fmaxf(fmaf(v, g_scale[128 + c], g_shift[128 + c]), 0.f);
        }
    }
}

// ------------------------- launch -------------------------
extern "C" void kernel_launch(void* const* d_in, const int* in_sizes, int n_in,
                              void* d_out, int out_size)
{
    const float* x      = (const float*)d_in[0];
    const float* coords = (const float*)d_in[1];
    const float* w1     = (const float*)d_in[2];
    const float* g1     = (const float*)d_in[3];
    const float* b1     = (const float*)d_in[4];
    const float* w2     = (const float*)d_in[5];
    const float* g2     = (const float*)d_in[6];
    const float* b2     = (const float*)d_in[7];
    float* out = (float*)d_out;

    cudaFuncSetAttribute(gemm_mma<0>, cudaFuncAttributeMaxDynamicSharedMemorySize, SMEM_P);
    cudaFuncSetAttribute(gemm_mma<1>, cudaFuncAttributeMaxDynamicSharedMemorySize, SMEM_P);

    zero_stats_kernel<<<1, 128>>>();
    transpose_kernel<<<dim3(NB, (NPTS + 15)/16), 256>>>(x);
    knn_kernel<<<dim3(NB, (NPTS + 7)/8), 256>>>(coords);
    gemm_mma<0><<<GRIDP, 512, SMEM_P>>>(w1);
    finalize_kernel<<<1, 128>>>(g1, b1, 0);
    gemm_mma<1><<<GRIDP, 512, SMEM_P>>>(w2);
    finalize_kernel<<<1, 128>>>(g2, b2, 1);
    final_kernel<<<dim3(NB, (NPTS + 31)/32, CC/32), 256>>>(out);
}